// round 13
// baseline (speedup 1.0000x reference)
#include <cuda_runtime.h>
#include <cstdint>

// ---------------- scratch (no allocations allowed) ----------------
#define B_ 16
#define C_ 21
#define D_ 512
#define HW_ 4096          // 64*64
#define LW_ 513
#define NV_ 336           // B_*C_ proto rows
#define GR_ 352           // padded to 11*32
#define KZ_ 2             // K-split factor (512/256)

__device__ unsigned char g_lab[B_ * HW_];            // resized labels as u8
__device__ float         g_sums[B_ * C_ * D_];       // pooled (unnormalized) sums
__device__ float         g_Spart[KZ_ * GR_ * GR_];   // partial Grams per K chunk
__device__ float         g_normsq[NV_];              // squared norms (k4a epilogue atomics)
__device__ float         g_pAll[C_ * C_];            // sum exp(S-10) per (c,e) block
__device__ float         g_pPos[C_];                 // sum of valid diag S values
__device__ int           g_pCnt[C_];                 // count of valid diag entries

// ---------------- K1: bilinear resize (half-pixel, exact) + normsq zeroing ----------------
__global__ void k1_resize(const int* __restrict__ labels) {
    int b = blockIdx.x;
    if (blockIdx.y == 0 && threadIdx.x < C_)
        g_normsq[b * C_ + threadIdx.x] = 0.0f;

    const int* L = labels + (size_t)b * LW_ * LW_;
    int base = blockIdx.y * 512;
    #pragma unroll
    for (int q = 0; q < 2; q++) {
        int p = base + q * 256 + threadIdx.x;
        int y = p >> 6, x = p & 63;
        // src = (i+0.5)*513/64 - 0.5 ; exact in fp32 (multiples of 1/128)
        float sy = (y + 0.5f) * 8.015625f - 0.5f;
        float sx = (x + 0.5f) * 8.015625f - 0.5f;
        int y0 = (int)sy; float wy = sy - (float)y0;
        int x0 = (int)sx; float wx = sx - (float)x0;
        const int* r0 = L + y0 * LW_ + x0;
        const int* r1 = r0 + LW_;
        float v00 = (float)r0[0], v01 = (float)r0[1];
        float v10 = (float)r1[0], v11 = (float)r1[1];
        float v = (1.0f - wy) * ((1.0f - wx) * v00 + wx * v01)
                +          wy * ((1.0f - wx) * v10 + wx * v11);
        int c = (int)v;   // truncation; v exact
        g_lab[b * HW_ + p] = (unsigned char)c;
    }
}

// ---------------- K2: masked per-class pooling (the 134 MB pass) ----------------
__global__ __launch_bounds__(256) void k2_pool(const float* __restrict__ feat) {
    int b   = blockIdx.x;
    int dt  = blockIdx.y;
    int tid = threadIdx.x;
    int w = tid >> 5, lane = tid & 31;

    __shared__ unsigned char slab[HW_];
    __shared__ float bins[8 * C_ * 32];

    ((uint4*)slab)[tid] = ((const uint4*)(g_lab + b * HW_))[tid];
    __syncthreads();

    int d = dt * 8 + w;
    float* bw = bins + w * (C_ * 32);

    #pragma unroll
    for (int c = 0; c < C_; c++) bw[c * 32 + lane] = 0.0f;

    const float4* F = (const float4*)(feat + ((size_t)(b * D_ + d)) * HW_);
    #pragma unroll 8
    for (int k = 0; k < 32; k++) {
        int p4 = k * 32 + lane;
        float4 f = __ldcs(&F[p4]);
        uchar4 lc = ((const uchar4*)slab)[p4];
        bw[lc.x * 32 + lane] += f.x;
        bw[lc.y * 32 + lane] += f.y;
        bw[lc.z * 32 + lane] += f.z;
        bw[lc.w * 32 + lane] += f.w;
    }
    __syncwarp();

    if (lane < C_) {
        float s = 0.0f;
        #pragma unroll
        for (int m = 0; m < 32; m++)
            s += bw[lane * 32 + ((m + lane) & 31)];
        g_sums[((size_t)(b * C_ + lane)) * D_ + d] = s;
    }
}

// ---------------- K4a: partial Gram SGEMM  U_z = S_z * S_z^T ----------------
__global__ __launch_bounds__(128) void k4a_gemm() {
    __shared__ float4 As4[32][32];   // [row][k4]
    __shared__ float4 Bs4[32][32];   // [k4][col]

    int t = threadIdx.x;
    int tr = t >> 4;
    int tc = t & 15;
    int rowBase = blockIdx.y * 32;
    int colBase = blockIdx.x * 32;
    int kz = blockIdx.z;

    float acc[4][2];
    #pragma unroll
    for (int r = 0; r < 4; r++) { acc[r][0] = 0.f; acc[r][1] = 0.f; }

    const float4* P4 = (const float4*)g_sums;   // row stride 128 f4

    #pragma unroll
    for (int kc = 0; kc < 2; kc++) {
        int kOff = kz * 64 + kc * 32;
        #pragma unroll
        for (int m = 0; m < 8; m++) {
            int idx = m * 128 + t;
            int row = idx >> 5, q = idx & 31;
            int v = rowBase + row;
            As4[row][q] = (v < NV_) ? P4[(size_t)v * 128 + kOff + q]
                                    : make_float4(0.f, 0.f, 0.f, 0.f);
        }
        #pragma unroll
        for (int m = 0; m < 8; m++) {
            int idx = m * 128 + t;
            int row = idx >> 5, q = idx & 31;
            int v = colBase + row;
            Bs4[q][row] = (v < NV_) ? P4[(size_t)v * 128 + kOff + q]
                                    : make_float4(0.f, 0.f, 0.f, 0.f);
        }
        __syncthreads();

        #pragma unroll 8
        for (int k4 = 0; k4 < 32; k4++) {
            float4 b0 = Bs4[k4][tc];
            float4 b1 = Bs4[k4][tc + 16];
            #pragma unroll
            for (int r = 0; r < 4; r++) {
                float4 a = As4[tr * 4 + r][k4];
                acc[r][0] = fmaf(a.x, b0.x, fmaf(a.y, b0.y, fmaf(a.z, b0.z, fmaf(a.w, b0.w, acc[r][0]))));
                acc[r][1] = fmaf(a.x, b1.x, fmaf(a.y, b1.y, fmaf(a.z, b1.z, fmaf(a.w, b1.w, acc[r][1]))));
            }
        }
        __syncthreads();
    }

    float* out = g_Spart + (size_t)kz * GR_ * GR_;
    #pragma unroll
    for (int r = 0; r < 4; r++) {
        int v = rowBase + tr * 4 + r;
        out[(size_t)v * GR_ + colBase + tc]      = acc[r][0];
        out[(size_t)v * GR_ + colBase + tc + 16] = acc[r][1];
    }

    if (rowBase == colBase) {
        #pragma unroll
        for (int r = 0; r < 4; r++) {
            int rl = tr * 4 + r;
            int v = rowBase + rl;
            if (v < NV_) {
                if (rl == tc)      atomicAdd(&g_normsq[v], acc[r][0]);
                if (rl == tc + 16) atomicAdd(&g_normsq[v], acc[r][1]);
            }
        }
    }
}

// ---------------- K4b: warp-per-cell exp-sum reduce ----------------
// 56 blocks x 256 threads; warp handles cell = bid*8 + warpId (441 cells).
// Lane l: j = l&15 fixed (vj, nsqj hoisted); folds 8 elements i = 2m + (l>=16).
__global__ __launch_bounds__(256) void k4b_reduce() {
    int tid  = threadIdx.x;
    int cell = blockIdx.x * 8 + (tid >> 5);
    if (cell >= C_ * C_) return;                 // whole warp uniform

    int c = cell / C_;
    int e = cell - c * C_;
    int lane = tid & 31;
    int j = lane & 15;
    int iOff = lane >> 4;                        // 0 or 1

    int vj = j * C_ + e;
    float nsqj = g_normsq[vj];
    bool okj = nsqj > 0.0f;
    float rnj = 1.0f / fmaxf(sqrtf(nsqj), 1e-12f);
    bool diag = (e == c);

    float term = 0.f, pos = 0.f, cnt = 0.f;
    #pragma unroll
    for (int m = 0; m < 8; m++) {
        int i = 2 * m + iOff;
        int vi = i * C_ + c;
        float nsqi = g_normsq[vi];
        float u = g_Spart[(size_t)vi * GR_ + vj]
                + g_Spart[(size_t)GR_ * GR_ + (size_t)vi * GR_ + vj];
        float rni = 1.0f / fmaxf(sqrtf(nsqi), 1e-12f);
        float dot = u * rni * rnj;
        bool valid = okj && (nsqi > 0.0f);
        float s = dot * 10.0f;                   // / T
        term += valid ? expf(s - 10.0f) : 0.0f;  // shift by 1/T (max possible)
        if (diag) {
            if (valid) { pos += s; cnt += 1.0f; }
        }
    }

    #pragma unroll
    for (int o = 16; o > 0; o >>= 1)
        term += __shfl_xor_sync(0xffffffffu, term, o);
    if (diag) {
        #pragma unroll
        for (int o = 16; o > 0; o >>= 1) {
            pos += __shfl_xor_sync(0xffffffffu, pos, o);
            cnt += __shfl_xor_sync(0xffffffffu, cnt, o);
        }
    }
    if (lane == 0) {
        g_pAll[cell] = term;
        if (diag) { g_pPos[c] = pos; g_pCnt[c] = (int)(cnt + 0.5f); }
    }
}

// ---------------- K5: per-class loss + total ----------------
__global__ void k5_final(float* __restrict__ out) {
    int c = threadIdx.x;
    float loss_c = 0.0f;
    if (c < C_) {
        int cnt = g_pCnt[c];
        if (cnt > 0) {                 // cls_present <=> diag count >= 1
            float sAll = 0.0f;
            #pragma unroll
            for (int e = 0; e < C_; e++) sAll += g_pAll[c * C_ + e];
            float sDiag = g_pAll[c * C_ + c];
            float lse = 10.0f + logf(sAll + sDiag);
            float pm = g_pPos[c] / (float)(cnt > 1 ? cnt : 1);
            loss_c = lse - pm;
        }
    }
    #pragma unroll
    for (int o = 16; o > 0; o >>= 1) loss_c += __shfl_xor_sync(0xffffffffu, loss_c, o);
    if (threadIdx.x == 0) out[0] = loss_c;
}

// ---------------- launch ----------------
extern "C" void kernel_launch(void* const* d_in, const int* in_sizes, int n_in,
                              void* d_out, int out_size) {
    const float* features = (const float*)d_in[0];   // [16,512,64,64] fp32
    const int*   labels   = (const int*)d_in[1];     // [16,513,513] int32
    float* out = (float*)d_out;

    k1_resize<<<dim3(B_, 8), 256>>>(labels);
    k2_pool<<<dim3(B_, D_ / 8), 256>>>(features);
    k4a_gemm<<<dim3(11, 11, KZ_), 128>>>();
    k4b_reduce<<<56, 256>>>();
    k5_final<<<1, 32>>>(out);
}